// round 1
// baseline (speedup 1.0000x reference)
#include <cuda_runtime.h>

#define BB 4
#define CC 32
#define HH 128
#define WW 240
#define JJ 15
#define HW (HH*WW)            // 30720
#define BHW (BB*HW)           // 122880
#define ROW 35                // 3 + C
#define WARP_FLOATS (32*ROW)  // 1120

// per-batch params: [0]=1/fx [1]=1/fy [2]=cx [3]=cy [4..15]=T(3x4) [16..27]=diff
__device__ float g_params[BB * 32];

__global__ void setup_params_kernel(const float* __restrict__ K,
                                    const float* __restrict__ M,
                                    const float* __restrict__ diff,
                                    const float* __restrict__ trans) {
    int b = threadIdx.x;
    if (b >= BB) return;
    const float* Kb = K + b * 9;
    float fxi = 1.0f / Kb[0];
    float fyi = 1.0f / Kb[4];
    float cx = Kb[2], cy = Kb[5];

    // Minv = [R^T, -R^T t; 0 1]
    const float* Mb = M + b * 16;
    float Minv[3][4];
    #pragma unroll
    for (int i = 0; i < 3; i++) {
        #pragma unroll
        for (int j = 0; j < 3; j++) Minv[i][j] = Mb[j * 4 + i];
        Minv[i][3] = -(Mb[0*4+i]*Mb[0*4+3] + Mb[1*4+i]*Mb[1*4+3] + Mb[2*4+i]*Mb[2*4+3]);
    }
    const float* Tr = trans + b * 16;
    float* P = g_params + b * 32;
    P[0] = fxi; P[1] = fyi; P[2] = cx; P[3] = cy;
    #pragma unroll
    for (int i = 0; i < 3; i++) {
        #pragma unroll
        for (int j = 0; j < 4; j++) {
            float s = 0.0f;
            #pragma unroll
            for (int k = 0; k < 3; k++) s += Tr[i*4+k] * Minv[k][j];
            if (j == 3) s += Tr[i*4+3];
            P[4 + i*4 + j] = s;
        }
    }
    #pragma unroll
    for (int i = 0; i < 12; i++) P[16 + i] = diff[b * 12 + i];
}

__global__ __launch_bounds__(128)
void get_3d_points_kernel(const float* __restrict__ depth_in,
                          const int*   __restrict__ mask_in,
                          const float* __restrict__ feat_in,
                          float*       __restrict__ out) {
    __shared__ float s_pc[4 * WARP_FLOATS];   // 17.9 KB: 4 warps x 32 points x 35 floats
    __shared__ int   s_mask[JJ * 128];        // 7.7 KB:  15 joints x 128 points

    const int tid  = threadIdx.x;
    const int lane = tid & 31;
    const int wrp  = tid >> 5;
    const int bp   = blockIdx.x * 128 + tid;  // grid = BHW/128 exactly
    const int b = bp / HW;
    const int p = bp - b * HW;
    const int hh = p / WW;
    const int ww = p - hh * WW;

    const float* P = g_params + b * 32;

    // pixel grid + K^-1
    float x  = (float)(ww + 71) * 4.0f;       // (w+71)*(1920/480)
    float y  = (float)hh * 8.4375f;           // h*(1080/128)
    float xb = (x - P[2]) * P[0];
    float yb = (y - P[3]) * P[1];

    float d0 = P[16], d1 = P[17], d2 = P[18], d3 = P[19];
    float d4 = P[20], d5 = P[21], d6 = P[22], d7 = P[23];
    float d8 = P[24], d9 = P[25], d10 = P[26], d11 = P[27];

    float xd = xb, yd = yb;
    #pragma unroll
    for (int it = 0; it < 5; it++) {
        float r2  = xd*xd + yd*yd;
        float num = 1.0f + ((d7*r2 + d6)*r2 + d5)*r2;
        float den = 1.0f + ((d4*r2 + d1)*r2 + d0)*r2;
        float ic  = num / den;
        float r4  = r2 * r2;
        float dX  = 2.0f*d2*xd*yd + d3*(r2 + 2.0f*xd*xd) + d8*r2 + d9*r4;
        float dY  = d2*(r2 + 2.0f*yd*yd) + 2.0f*d3*xd*yd + d10*r2 + d11*r4;
        xd = (xb - dX) * ic;
        yd = (yb - dY) * ic;
    }

    float dep = depth_in[bp];
    float X4 = xd * dep, Y4 = yd * dep;
    float px = P[4]*X4  + P[5]*Y4  + P[6]*dep  + P[7];
    float py = P[8]*X4  + P[9]*Y4  + P[10]*dep + P[11];
    float pz = P[12]*X4 + P[13]*Y4 + P[14]*dep + P[15];

    // stage this warp's 32 rows (stride 35 words -> conflict-free, gcd(35,32)=1)
    float* row = s_pc + wrp * WARP_FLOATS + lane * ROW;
    row[0] = px; row[1] = py; row[2] = pz;
    const float* fb = feat_in + (size_t)b * (CC * HW) + p;
    #pragma unroll
    for (int c = 0; c < CC; c++) row[3 + c] = fb[(size_t)c * HW];

    #pragma unroll
    for (int j = 0; j < JJ; j++)
        s_mask[j * 128 + tid] = mask_in[(size_t)j * BHW + bp];

    __syncwarp();

    // coalesced masked broadcast: 280 float4 per warp per joint
    const float4* src = (const float4*)(s_pc + wrp * WARP_FLOATS);
    const long warp_bp = (long)blockIdx.x * 128 + wrp * 32;

    #pragma unroll 1
    for (int j = 0; j < JJ; j++) {
        float4* dst = (float4*)(out + ((long)j * BHW + warp_bp) * ROW);
        const int* mrow = s_mask + j * 128 + wrp * 32;
        #pragma unroll
        for (int i = 0; i < 9; i++) {
            int chunk = i * 32 + lane;
            if (chunk < 280) {
                int s = chunk * 4;
                int q = s / 35;              // local point 0..31
                int rem = s - q * 35;
                float4 v = src[chunk];
                int m0 = mrow[q];
                int bnd = 35 - rem;          // elems with idx < bnd belong to q
                if (bnd >= 4) {
                    if (!m0) { v.x = 0.f; v.y = 0.f; v.z = 0.f; v.w = 0.f; }
                } else {
                    int m1 = mrow[q + 1];
                    float f0 = m0 ? 1.0f : 0.0f;
                    float f1 = m1 ? 1.0f : 0.0f;
                    v.x *= (0 < bnd ? f0 : f1);
                    v.y *= (1 < bnd ? f0 : f1);
                    v.z *= (2 < bnd ? f0 : f1);
                    v.w *= (3 < bnd ? f0 : f1);
                }
                dst[chunk] = v;
            }
        }
    }
}

extern "C" void kernel_launch(void* const* d_in, const int* in_sizes, int n_in,
                              void* d_out, int out_size) {
    const float* depth = (const float*)d_in[0];   // pred_depth [B,1,H,W]
    const int*   mask  = (const int*)  d_in[1];   // filter_mask [J,B,H,W] int32
    const float* K     = (const float*)d_in[2];   // [B,3,3]
    const float* M     = (const float*)d_in[3];   // [B,4,4]
    const float* diff  = (const float*)d_in[4];   // [B,12]
    const float* trans = (const float*)d_in[5];   // [B,4,4]
    const float* feat  = (const float*)d_in[6];   // [B,C,H,W]
    // d_in[7], d_in[8]: orig_W=1920, orig_H=1080 (compile-time constants in grid math)

    setup_params_kernel<<<1, 32>>>(K, M, diff, trans);
    get_3d_points_kernel<<<BHW / 128, 128>>>(depth, mask, feat, (float*)d_out);
}